// round 10
// baseline (speedup 1.0000x reference)
#include <cuda_runtime.h>
#include <cstdint>

// AttentionDownsampler v10: single fused launch, producer/consumer conveyor.
//  Producers (bids 0..63, all resident in wave 1, never wait): each runs 4
//  half-slab pixel-dot+softmax units in slab-ascending order -> g_attnT,
//  flagging g_done[slab]. Slabs complete progressively in 38MB stages.
//  Consumers (bids 64.., slab-ordered): spin until their slab's attn is
//  ready, then stream their 32-channel chunk -- which the producer read
//  moments earlier, so these reads hit L2 instead of DRAM.
// DRAM traffic ~154MB (was 308MB); LTS 308MB is the new bound.

#define DIM     384
#define KS      7
#define NP      49
#define HW      112
#define PLANE   (HW * HW)
#define PLANE4  (PLANE / 4)
#define FN      16
#define NSLAB   128
#define SLABPIX 784
#define DROP_P  0.2f

#define NPROD   64                // producer CTAs; 4 units each (256 units)
#define CPGO    32                // channels per consumer CTA
#define NCG2    12                // 384 / 32
#define NCONS   (NSLAB * NCG2)    // 1536
#define TB      448

__device__ float g_attnT[(size_t)NSLAB * SLABPIX];  // [slab][dy*112 + x]
__device__ int   g_done[NSLAB];

__global__ void zero_flags_kernel()
{
    if (threadIdx.x < NSLAB) g_done[threadIdx.x] = 0;
}

__global__ void __launch_bounds__(TB, 2)
fused_kernel(const float* __restrict__ hr,
             const float* __restrict__ du,
             const float* __restrict__ aw,
             const float* __restrict__ ab,
             const float* __restrict__ wmat,
             const float* __restrict__ bmat,
             float* __restrict__ out)
{
    const int bid = blockIdx.x;
    const int tid = threadIdx.x;

    if (bid < NPROD) {
        // ================= producer: pixel dot + softmax =================
        __shared__ float awsh[DIM];
        __shared__ float pd_s[392];

        const bool act = tid < 392;
        int qr = 0, dy = 0, x4l = 0;
        if (act) {
            qr = tid / 98;                   // channel quarter 0..3
            const int pos = tid - qr * 98;   // dy*14 + x4l
            dy  = pos / 14;
            x4l = pos - dy * 14;
        }
        if (tid < DIM) awsh[tid] = __ldg(aw + tid);
        __syncthreads();

        #pragma unroll
        for (int j = 0; j < 4; j++) {
            const int unit = bid + NPROD * j;     // slab-ascending stages
            const int xh   = unit & 1;
            const int slab = unit >> 1;
            const int ph   = slab & (FN - 1);
            const int b    = slab >> 4;

            if (act) pd_s[tid] = 0.f;
            __syncthreads();

            if (act) {
                const float4* gp = (const float4*)(hr
                    + (size_t)(b * DIM + qr * 96) * PLANE
                    + (size_t)(ph * KS + dy) * HW) + (xh * 14 + x4l);
                const float* ap = awsh + qr * 96;
                float4 acc = make_float4(0.f, 0.f, 0.f, 0.f);
                #pragma unroll 8
                for (int t = 0; t < 96; t++) {
                    float4 v = __ldg(gp + (size_t)t * PLANE4);
                    const float a = ap[t];
                    acc.x = fmaf(v.x, a, acc.x);
                    acc.y = fmaf(v.y, a, acc.y);
                    acc.z = fmaf(v.z, a, acc.z);
                    acc.w = fmaf(v.w, a, acc.w);
                }
                float* pc = pd_s + dy * 56 + x4l * 4;
                atomicAdd(pc + 0, acc.x);
                atomicAdd(pc + 1, acc.y);
                atomicAdd(pc + 2, acc.z);
                atomicAdd(pc + 3, acc.w);
            }
            __syncthreads();

            // softmax: warp w (0..7) handles patch pw = xh*8 + w
            const int wid = tid >> 5, lane = tid & 31;
            if (wid < 8) {
                const int pw = xh * 8 + wid;
                const float m   = (__ldg(du + (b * FN + ph) * FN + pw) > DROP_P) ? 1.f : 0.f;
                const float abv = __ldg(ab);
                const int p0 = lane, p1 = lane + 32;
                float v0 = -1e30f, v1 = -1e30f;
                if (p0 < NP) {
                    int d = p0 / KS, e = p0 - d * KS;
                    v0 = (pd_s[d * 56 + wid * KS + e] + abv) * m * __ldg(wmat + p0) + __ldg(bmat + p0);
                }
                if (p1 < NP) {
                    int d = p1 / KS, e = p1 - d * KS;
                    v1 = (pd_s[d * 56 + wid * KS + e] + abv) * m * __ldg(wmat + p1) + __ldg(bmat + p1);
                }
                float mx = fmaxf(v0, v1);
                #pragma unroll
                for (int o = 16; o; o >>= 1)
                    mx = fmaxf(mx, __shfl_xor_sync(0xffffffffu, mx, o));
                float e0 = (p0 < NP) ? __expf(v0 - mx) : 0.f;
                float e1 = (p1 < NP) ? __expf(v1 - mx) : 0.f;
                float ss = e0 + e1;
                #pragma unroll
                for (int o = 16; o; o >>= 1)
                    ss += __shfl_xor_sync(0xffffffffu, ss, o);
                const float inv = 1.f / ss;
                float* dstT = g_attnT + (size_t)slab * SLABPIX;
                if (p0 < NP) {
                    int d = p0 / KS, e = p0 - d * KS;
                    dstT[d * HW + pw * KS + e] = e0 * inv;
                }
                if (p1 < NP) {
                    int d = p1 / KS, e = p1 - d * KS;
                    dstT[d * HW + pw * KS + e] = e1 * inv;
                }
            }
            __syncthreads();
            if (tid == 0) {
                __threadfence();
                atomicAdd(&g_done[slab], 1);
            }
        }
        return;
    }

    // ================= consumer: register epilogue ======================
    __shared__ float out_s[CPGO * FN];       // [32ch][16pw]

    const int bid2  = bid - NPROD;
    const int slab  = bid2 / NCG2;
    const int cg    = bid2 - slab * NCG2;
    const int ph    = slab & (FN - 1);
    const int b     = slab >> 4;
    const int cbase = cg * CPGO;

    const int x4 = tid % 28;
    const int cc = tid / 28;

    for (int i = tid; i < CPGO * FN; i += TB) out_s[i] = 0.f;

    // wait until this slab's attention weights are published
    if (tid == 0) {
        while (atomicAdd(&g_done[slab], 0) < 2) __nanosleep(64);
    }
    __syncthreads();
    __threadfence();

    // 7 aligned float4 coefficient loads (L2-hot)
    const float4* cp = (const float4*)(g_attnT + (size_t)slab * SLABPIX) + x4;
    float4 coef[KS];
    #pragma unroll
    for (int d = 0; d < KS; d++)
        coef[d] = __ldg(cp + d * 28);

    int pwk[4];
    #pragma unroll
    for (int k = 0; k < 4; k++) pwk[k] = (4 * x4 + k) / KS;

    const float* base = hr + (size_t)(b * DIM + cbase + cc) * PLANE
                           + (size_t)(ph * KS) * HW;

    #pragma unroll
    for (int g = 0; g < 2; g++) {
        const float4* gp = (const float4*)(base + (size_t)(g * 16) * PLANE) + x4;
        float4 v[KS];
        #pragma unroll
        for (int d = 0; d < KS; d++)
            v[d] = __ldg(gp + d * 28);

        float acc[4] = {0.f, 0.f, 0.f, 0.f};
        #pragma unroll
        for (int d = 0; d < KS; d++) {
            acc[0] = fmaf(v[d].x, coef[d].x, acc[0]);
            acc[1] = fmaf(v[d].y, coef[d].y, acc[1]);
            acc[2] = fmaf(v[d].z, coef[d].z, acc[2]);
            acc[3] = fmaf(v[d].w, coef[d].w, acc[3]);
        }
        float* orow = out_s + (g * 16 + cc) * FN;
        int   cur = pwk[0];
        float a   = acc[0];
        #pragma unroll
        for (int k = 1; k < 4; k++) {
            if (pwk[k] == cur) a += acc[k];
            else { atomicAdd(&orow[cur], a); cur = pwk[k]; a = acc[k]; }
        }
        atomicAdd(&orow[cur], a);
    }
    __syncthreads();

    for (int i = tid; i < CPGO * FN; i += TB) {
        const int lc = i >> 4, pw = i & 15;
        out[((size_t)(b * DIM + cbase + lc) * FN + ph) * FN + pw] = out_s[i];
    }
}

extern "C" void kernel_launch(void* const* d_in, const int* in_sizes, int n_in,
                              void* d_out, int out_size)
{
    const float* hr   = (const float*)d_in[0];   // (8,384,112,112)
    // d_in[1] = guidance (unused)
    const float* du   = (const float*)d_in[2];   // (8,16,16,1)
    const float* aw   = (const float*)d_in[3];   // (384,)
    const float* ab   = (const float*)d_in[4];   // (1,)
    const float* wmat = (const float*)d_in[5];   // (7,7)
    const float* bmat = (const float*)d_in[6];   // (7,7)
    float* out = (float*)d_out;                  // (8,384,16,16)

    zero_flags_kernel<<<1, NSLAB>>>();
    fused_kernel<<<NPROD + NCONS, TB>>>(hr, du, aw, ab, wmat, bmat, out);
}

// round 13
// speedup vs baseline: 1.0450x; 1.0450x over previous
#include <cuda_runtime.h>
#include <cooperative_groups.h>
#include <cstdint>

namespace cg = cooperative_groups;

// AttentionDownsampler v11: single kernel, CGA cluster of 8, hr read ONCE.
// Cluster = one half-slab (b, ph, xh): 8 patches, self-contained softmax.
// Rank r owns 48 channels: stages 48ch x 7dy x 56x in smem (75KB), computes
// its pixel-dot partial; ranks exchange partials + attn via DSMEM with
// cluster.sync (co-residency guaranteed -- no spin deadlock/starvation).
// Epilogue runs from the local smem tile. Total LTS traffic ~154MB (1x).

#define DIM     384
#define KS      7
#define NP      49
#define HW      112
#define PLANE   (HW * HW)
#define FN      16
#define DROP_P  0.2f

#define CLN     8                 // cluster size (portable)
#define CPG     48                // channels per CTA
#define XH      56                // half-slab width
#define HPIX    392               // 7 * 56 pixels
#define TB      336               // (x4:14, cc:24); 2 channels/thread

// smem carve (floats)
#define TILE_F   (CPG * HPIX)     // 18816
#define OFF_PD   TILE_F           // [392]
#define OFF_AW   (OFF_PD + HPIX)  // [48]
#define OFF_LSH  (OFF_AW + CPG)   // [64]
#define OFF_AM   (OFF_LSH + 64)   // [64] attn_mine (49 used)
#define OFF_AT   (OFF_AM + 64)    // [392] attnT
#define OFF_OUT  (OFF_AT + HPIX)  // [48*8]
#define SMEM_F   (OFF_OUT + CPG * 8)
#define SMEM_B   (SMEM_F * 4)     // ~82KB -> 2 CTAs/SM

__global__ void __launch_bounds__(TB, 2) __cluster_dims__(CLN, 1, 1)
fused_cluster_kernel(const float* __restrict__ hr,
                     const float* __restrict__ du,
                     const float* __restrict__ aw,
                     const float* __restrict__ ab,
                     const float* __restrict__ wmat,
                     const float* __restrict__ bmat,
                     float* __restrict__ out)
{
    extern __shared__ float sm[];
    float* tile   = sm;
    float* pd_s   = sm + OFF_PD;
    float* awsh   = sm + OFF_AW;
    float* lsh    = sm + OFF_LSH;
    float* am_s   = sm + OFF_AM;
    float* attnT  = sm + OFF_AT;
    float* out_s  = sm + OFF_OUT;

    cg::cluster_group cl = cg::this_cluster();

    const int bid  = blockIdx.x;
    const int rank = bid & (CLN - 1);
    const int cid  = bid >> 3;           // (slab, xh)
    const int xh   = cid & 1;
    const int slab = cid >> 1;
    const int ph   = slab & (FN - 1);
    const int b    = slab >> 4;

    const int tid = threadIdx.x;
    const int x4  = tid % 14;            // float4 col within half (0..13)
    const int cc  = tid / 14;            // 0..23, channels cc & cc+24

    if (tid < CPG) awsh[tid] = __ldg(aw + rank * CPG + tid);
    for (int i = tid; i < CPG * 8; i += TB) out_s[i] = 0.f;

    // ---- phase 1: stage tile (14 LDG.128/thread, rows 224B) ----
    #pragma unroll
    for (int h = 0; h < 2; h++) {
        const int lc = cc + 24 * h;
        const float* gr = hr + (size_t)(b * DIM + rank * CPG + lc) * PLANE
                             + (size_t)(ph * KS) * HW + xh * XH;
        const float4* gp = (const float4*)gr + x4;
        float* tr = tile + lc * HPIX + x4 * 4;
        #pragma unroll
        for (int dy = 0; dy < KS; dy++)
            *(float4*)(tr + dy * XH) = __ldg(gp + dy * 28);
    }
    __syncthreads();

    // ---- pixel-dot partial over this CTA's 48 channels ----
    for (int p = tid; p < HPIX; p += TB) {
        float s = 0.f;
        #pragma unroll
        for (int c2 = 0; c2 < CPG; c2++)
            s = fmaf(tile[c2 * HPIX + p], awsh[c2], s);
        pd_s[p] = s;
    }
    cl.sync();

    // ---- rank r: gather its patch (pw local = rank) + softmax ----
    if (tid < NP) {
        const int dy = tid / KS, dx = tid - (tid / KS) * KS;
        const int idx = dy * XH + rank * KS + dx;
        float s = 0.f;
        #pragma unroll
        for (int r2 = 0; r2 < CLN; r2++)
            s += *(cl.map_shared_rank(pd_s, r2) + idx);
        lsh[tid] = s;
    }
    __syncthreads();

    if (tid < 32) {
        const int lane = tid;
        const int pw   = xh * 8 + rank;
        const float m   = (__ldg(du + (b * FN + ph) * FN + pw) > DROP_P) ? 1.f : 0.f;
        const float abv = __ldg(ab);
        const int p0 = lane, p1 = lane + 32;
        float v0 = -1e30f, v1 = -1e30f;
        if (p0 < NP) v0 = (lsh[p0] + abv) * m * __ldg(wmat + p0) + __ldg(bmat + p0);
        if (p1 < NP) v1 = (lsh[p1] + abv) * m * __ldg(wmat + p1) + __ldg(bmat + p1);
        float mx = fmaxf(v0, v1);
        #pragma unroll
        for (int o = 16; o; o >>= 1)
            mx = fmaxf(mx, __shfl_xor_sync(0xffffffffu, mx, o));
        float e0 = (p0 < NP) ? __expf(v0 - mx) : 0.f;
        float e1 = (p1 < NP) ? __expf(v1 - mx) : 0.f;
        float ss = e0 + e1;
        #pragma unroll
        for (int o = 16; o; o >>= 1)
            ss += __shfl_xor_sync(0xffffffffu, ss, o);
        const float inv = 1.f / ss;
        if (p0 < NP) am_s[p0] = e0 * inv;
        if (p1 < NP) am_s[p1] = e1 * inv;
    }
    __syncthreads();
    cl.sync();

    // ---- assemble transposed coef table from peers ----
    for (int p = tid; p < HPIX; p += TB) {
        const int dyq = p / XH;
        const int xl  = p - dyq * XH;
        const int pwl = xl / KS;          // owner rank
        attnT[p] = *(cl.map_shared_rank(am_s, pwl) + dyq * KS + (xl - pwl * KS));
    }
    __syncthreads();
    cl.sync();                            // peers done reading am_s / pd_s

    // ---- epilogue from local tile ----
    float coef[KS][4];
    #pragma unroll
    for (int dy = 0; dy < KS; dy++)
        #pragma unroll
        for (int k = 0; k < 4; k++)
            coef[dy][k] = attnT[dy * XH + 4 * x4 + k];
    int pwk[4];
    #pragma unroll
    for (int k = 0; k < 4; k++) pwk[k] = (4 * x4 + k) / KS;

    #pragma unroll
    for (int h = 0; h < 2; h++) {
        const int lc = cc + 24 * h;
        const float* tr = tile + lc * HPIX + x4 * 4;
        float acc[4] = {0.f, 0.f, 0.f, 0.f};
        #pragma unroll
        for (int dy = 0; dy < KS; dy++) {
            float4 v = *(const float4*)(tr + dy * XH);
            acc[0] = fmaf(v.x, coef[dy][0], acc[0]);
            acc[1] = fmaf(v.y, coef[dy][1], acc[1]);
            acc[2] = fmaf(v.z, coef[dy][2], acc[2]);
            acc[3] = fmaf(v.w, coef[dy][3], acc[3]);
        }
        float* orow = out_s + lc * 8;
        int   cur = pwk[0];
        float a   = acc[0];
        #pragma unroll
        for (int k = 1; k < 4; k++) {
            if (pwk[k] == cur) a += acc[k];
            else { atomicAdd(&orow[cur], a); cur = pwk[k]; a = acc[k]; }
        }
        atomicAdd(&orow[cur], a);
    }
    __syncthreads();

    for (int i = tid; i < CPG * 8; i += TB) {
        const int lc = i >> 3, pwl = i & 7;
        const int pw = xh * 8 + pwl;
        out[((size_t)(b * DIM + rank * CPG + lc) * FN + ph) * FN + pw] = out_s[i];
    }
}

extern "C" void kernel_launch(void* const* d_in, const int* in_sizes, int n_in,
                              void* d_out, int out_size)
{
    const float* hr   = (const float*)d_in[0];   // (8,384,112,112)
    // d_in[1] = guidance (unused)
    const float* du   = (const float*)d_in[2];   // (8,16,16,1)
    const float* aw   = (const float*)d_in[3];   // (384,)
    const float* ab   = (const float*)d_in[4];   // (1,)
    const float* wmat = (const float*)d_in[5];   // (7,7)
    const float* bmat = (const float*)d_in[6];   // (7,7)
    float* out = (float*)d_out;                  // (8,384,16,16)

    cudaFuncSetAttribute(fused_cluster_kernel,
                         cudaFuncAttributeMaxDynamicSharedMemorySize, SMEM_B);

    // 128 slabs x 2 halves x 8 ranks = 2048 CTAs, clusters of 8
    fused_cluster_kernel<<<2048, TB, SMEM_B>>>(hr, du, aw, ab, wmat, bmat, out);
}

// round 14
// speedup vs baseline: 1.4508x; 1.3882x over previous
#include <cuda_runtime.h>
#include <cstdint>

// AttentionDownsampler v12: v9 split kernels with balanced grids.
//  K1: quarter-slab CTAs (28 cols = 4 whole patches) -> grid 512, 4 CTAs/SM,
//      single wave, every SM loaded 3-4 CTAs (was: 256 CTAs, 40% imbalance).
//  K3: half-slab-x units (32ch x 56 cols) -> grid 3072, 10.4 waves, ~6% tail
//      (was 1536 / 5.19 waves / 16% tail). Inner streaming core unchanged.

#define DIM     384
#define KS      7
#define NP      49
#define HW      112
#define PLANE   (HW * HW)
#define PLANE4  (PLANE / 4)
#define FN      16
#define NSLAB   128
#define SLABPIX 784
#define DROP_P  0.2f

// K1 geometry: CTA = (slab, x-quarter of 28 cols)
#define T1      224               // (qr:4, dy:7, x4:7) = 196 active
// K3 geometry: CTA = (slab, xh, cg): 32 channels x 56 cols
#define CPGO    32
#define NCG2    12
#define XH      56
#define T3      448               // (x4:14, cc:32)

__device__ float g_attnT[(size_t)NSLAB * SLABPIX];  // [slab][dy*112 + x]

// ================= K1: pixel dot + softmax (quarter-slab) ================
__global__ void __launch_bounds__(T1, 4)
k1_dot_softmax(const float* __restrict__ hr,
               const float* __restrict__ du,
               const float* __restrict__ aw,
               const float* __restrict__ ab,
               const float* __restrict__ wmat,
               const float* __restrict__ bmat)
{
    __shared__ float awsh[DIM];
    __shared__ float pd_s[KS * 28];      // [dy][28]

    const int bid  = blockIdx.x;
    const int xq   = bid & 3;            // x-quarter: cols [xq*28, xq*28+28)
    const int slab = bid >> 2;
    const int ph   = slab & (FN - 1);
    const int b    = slab >> 4;

    const int tid = threadIdx.x;
    const bool act = tid < 196;
    int qr = 0, dy = 0, x4 = 0;
    if (act) {
        qr = tid / 49;                   // channel quarter 0..3
        const int pos = tid - qr * 49;   // dy*7 + x4
        dy = pos / 7;
        x4 = pos - dy * 7;
    }

    for (int i = tid; i < DIM; i += T1) awsh[i] = __ldg(aw + i);
    if (tid < KS * 28) pd_s[tid] = 0.f;
    __syncthreads();

    if (act) {
        const float4* gp = (const float4*)(hr
            + (size_t)(b * DIM + qr * 96) * PLANE
            + (size_t)(ph * KS + dy) * HW) + (xq * 7 + x4);
        const float* ap = awsh + qr * 96;
        float4 acc = make_float4(0.f, 0.f, 0.f, 0.f);
        #pragma unroll 8
        for (int t = 0; t < 96; t++) {
            float4 v = __ldg(gp + (size_t)t * PLANE4);
            const float a = ap[t];
            acc.x = fmaf(v.x, a, acc.x);
            acc.y = fmaf(v.y, a, acc.y);
            acc.z = fmaf(v.z, a, acc.z);
            acc.w = fmaf(v.w, a, acc.w);
        }
        float* pc = pd_s + dy * 28 + x4 * 4;     // 4 qr contributors/cell
        atomicAdd(pc + 0, acc.x);
        atomicAdd(pc + 1, acc.y);
        atomicAdd(pc + 2, acc.z);
        atomicAdd(pc + 3, acc.w);
    }
    __syncthreads();

    // softmax: warp w (0..3) handles patch pw = xq*4 + w; write transposed
    const int wid = tid >> 5, lane = tid & 31;
    if (wid < 4) {
        const int pw = xq * 4 + wid;
        const float m   = (__ldg(du + (b * FN + ph) * FN + pw) > DROP_P) ? 1.f : 0.f;
        const float abv = __ldg(ab);
        const int p0 = lane, p1 = lane + 32;
        float v0 = -1e30f, v1 = -1e30f;
        if (p0 < NP) {
            int d = p0 / KS, e = p0 - d * KS;
            v0 = (pd_s[d * 28 + wid * KS + e] + abv) * m * __ldg(wmat + p0) + __ldg(bmat + p0);
        }
        if (p1 < NP) {
            int d = p1 / KS, e = p1 - d * KS;
            v1 = (pd_s[d * 28 + wid * KS + e] + abv) * m * __ldg(wmat + p1) + __ldg(bmat + p1);
        }
        float mx = fmaxf(v0, v1);
        #pragma unroll
        for (int o = 16; o; o >>= 1)
            mx = fmaxf(mx, __shfl_xor_sync(0xffffffffu, mx, o));
        float e0 = (p0 < NP) ? __expf(v0 - mx) : 0.f;
        float e1 = (p1 < NP) ? __expf(v1 - mx) : 0.f;
        float ss = e0 + e1;
        #pragma unroll
        for (int o = 16; o; o >>= 1)
            ss += __shfl_xor_sync(0xffffffffu, ss, o);
        const float inv = 1.f / ss;
        float* dstT = g_attnT + (size_t)slab * SLABPIX + xq * 28;
        if (p0 < NP) {
            int d = p0 / KS, e = p0 - d * KS;
            dstT[d * HW + wid * KS + e] = e0 * inv;
        }
        if (p1 < NP) {
            int d = p1 / KS, e = p1 - d * KS;
            dstT[d * HW + wid * KS + e] = e1 * inv;
        }
    }
}

// ================= K3: register epilogue (half-slab-x units) =============
__global__ void __launch_bounds__(T3, 2)
k3_epilogue(const float* __restrict__ hr, float* __restrict__ out)
{
    __shared__ float out_s[CPGO * 8];    // [32ch][8 local pw]

    const int bid   = blockIdx.x;
    const int slab  = bid / (NCG2 * 2);
    const int rem   = bid - slab * (NCG2 * 2);
    const int cg    = rem >> 1;
    const int xh    = rem & 1;           // x half: cols [xh*56, xh*56+56)
    const int ph    = slab & (FN - 1);
    const int b     = slab >> 4;
    const int cbase = cg * CPGO;

    const int tid = threadIdx.x;
    const int x4  = tid % 14;            // float4 col within half
    const int cc  = tid / 14;            // channel 0..31

    for (int i = tid; i < CPGO * 8; i += T3) out_s[i] = 0.f;

    // 7 aligned float4 coefficient loads (L2/L1-hot)
    const float4* cp = (const float4*)(g_attnT + (size_t)slab * SLABPIX
                                       + xh * XH) + x4;
    float4 coef[KS];
    #pragma unroll
    for (int d = 0; d < KS; d++)
        coef[d] = __ldg(cp + d * 28);

    // local pw (0..7) for this thread's 4 x positions
    int pwk[4];
    #pragma unroll
    for (int k = 0; k < 4; k++) pwk[k] = (xh * XH + 4 * x4 + k) / KS - xh * 8;

    const float4* gp = (const float4*)(hr
        + (size_t)(b * DIM + cbase + cc) * PLANE
        + (size_t)(ph * KS) * HW + xh * XH) + x4;
    __syncthreads();                      // out_s zeroed

    float4 v[KS];
    #pragma unroll
    for (int d = 0; d < KS; d++)
        v[d] = __ldg(gp + d * 28);

    float acc[4] = {0.f, 0.f, 0.f, 0.f};
    #pragma unroll
    for (int d = 0; d < KS; d++) {
        acc[0] = fmaf(v[d].x, coef[d].x, acc[0]);
        acc[1] = fmaf(v[d].y, coef[d].y, acc[1]);
        acc[2] = fmaf(v[d].z, coef[d].z, acc[2]);
        acc[3] = fmaf(v[d].w, coef[d].w, acc[3]);
    }
    {
        float* orow = out_s + cc * 8;
        int   cur = pwk[0];
        float a   = acc[0];
        #pragma unroll
        for (int k = 1; k < 4; k++) {
            if (pwk[k] == cur) a += acc[k];
            else { atomicAdd(&orow[cur], a); cur = pwk[k]; a = acc[k]; }
        }
        atomicAdd(&orow[cur], a);
    }
    __syncthreads();

    for (int i = tid; i < CPGO * 8; i += T3) {
        const int lc = i >> 3, pwl = i & 7;
        const int pw = xh * 8 + pwl;
        out[((size_t)(b * DIM + cbase + lc) * FN + ph) * FN + pw] = out_s[i];
    }
}

extern "C" void kernel_launch(void* const* d_in, const int* in_sizes, int n_in,
                              void* d_out, int out_size)
{
    const float* hr   = (const float*)d_in[0];   // (8,384,112,112)
    // d_in[1] = guidance (unused)
    const float* du   = (const float*)d_in[2];   // (8,16,16,1)
    const float* aw   = (const float*)d_in[3];   // (384,)
    const float* ab   = (const float*)d_in[4];   // (1,)
    const float* wmat = (const float*)d_in[5];   // (7,7)
    const float* bmat = (const float*)d_in[6];   // (7,7)
    float* out = (float*)d_out;                  // (8,384,16,16)

    k1_dot_softmax<<<NSLAB * 4, T1>>>(hr, du, aw, ab, wmat, bmat);
    k3_epilogue<<<NSLAB * NCG2 * 2, T3>>>(hr, out);
}